// round 8
// baseline (speedup 1.0000x reference)
#include <cuda_runtime.h>
#include <cuda_fp16.h>
#include <cstdint>
#include <cstddef>

// Problem constants: B=4, I=64, O=64, K=3, H=W=512.
#define EPS_F 1e-8f

// ---------------------------------------------------------------------------
// Device scratch.
// ---------------------------------------------------------------------------
// Input transposed to HWC fp16: g_hwc[b][y][x][i], 128 B per pixel.
__device__ __align__(16) __half g_hwc[(size_t)4 * 512 * 512 * 64];   // 128 MB
// Modulated weights packed for LDS.64 B-fetch:
// g_wB[b][t(4)][ks(36)][col=o(64)][2 words]; for K16-step ks, word0 = half2 of
// kpair row (8*ks + t), word1 = kpair row (8*ks + t + 4).
__device__ __align__(16) uint32_t g_wB[4 * 4 * 36 * 64 * 2];         // 294 KB
// Progress flags: [0..127] = transpose stripe arrive counters (target 128 CTAs),
// [128] = modulate arrive counter (target 32 CTAs).
__device__ uint32_t g_flags[129];

static constexpr int N_PROD    = 128;   // producer CTAs (transpose+modulate)
static constexpr int N_CONS    = 8192;  // conv CTAs
static constexpr int MOD_CTAS  = 32;    // producer CTAs that also modulate

__device__ __forceinline__ uint32_t smem_u32(const void* p) {
    uint32_t a;
    asm("{ .reg .u64 t; cvta.to.shared.u64 t, %1; cvt.u32.u64 %0, t; }"
        : "=r"(a) : "l"(p));
    return a;
}
__device__ __forceinline__ uint32_t ld_acq(const uint32_t* p) {
    uint32_t v;
    asm volatile("ld.acquire.gpu.global.b32 %0, [%1];" : "=r"(v) : "l"(p));
    return v;
}
__device__ __forceinline__ void red_release(uint32_t* p) {
    asm volatile("red.release.gpu.global.add.u32 [%0], %1;"
                 :: "l"(p), "r"(1u) : "memory");
}
#define WAIT_GE(flagref, target) \
    do { while (ld_acq(&(flagref)) < (target)) __nanosleep(128); } while (0)

// ---------------------------------------------------------------------------
// Kernel 0: zero the progress flags (runs before the fused kernel each call).
// ---------------------------------------------------------------------------
__global__ void zero_flags_kernel() {
    if (threadIdx.x < 129) g_flags[threadIdx.x] = 0;
}

// ---------------------------------------------------------------------------
// Fused kernel.
// bids [0, 128):    producers. Bids [0,32) first modulate (1 warp = 1 (b,o)),
//                   then all 128 sweep the NCHW fp32 -> HWC fp16 transpose in
//                   128 stripes of (b, 16 rows), publishing per-stripe flags.
// bids [128, 8320): consumers = round-7 conv CTAs, spinning on the stripe
//                   flags covering their 10-row halo before loading A.
// ---------------------------------------------------------------------------
static constexpr int ASH_BYTES  = 180 * 144;              // 25920
static constexpr int B_TSTRIDE  = 36 * 64 * 2 + 8;        // 4616 words per t block
static constexpr int BSH_BYTES  = 4 * B_TSTRIDE * 4;      // 73856
static constexpr int CONV_SMEM  = ASH_BYTES + BSH_BYTES;  // 99776

__global__ __launch_bounds__(256, 2)
void fused_kernel(const float* __restrict__ input,    // (4, 64, 512, 512) fp32
                  const float* __restrict__ weight,   // (64, 64, 3, 3)
                  const float* __restrict__ style,    // (4, 64)
                  float* __restrict__ out) {          // (4, 64, 512, 512)
    const int bid  = blockIdx.x;
    const int tid  = threadIdx.x;
    const int lane = tid & 31;
    const int wid  = tid >> 5;

    // =======================================================================
    // PRODUCER PATH
    // =======================================================================
    if (bid < N_PROD) {
        // ---- modulate: warp w handles (b,o) = (w>>6, w&63) ----
        const int w = bid * 8 + wid;
        if (w < 256) {
            const int b = w >> 6;
            const int o = w & 63;
            float sum = 0.f;
            #pragma unroll
            for (int j = 0; j < 18; j++) {
                const int idx = j * 32 + lane;            // 0..575
                const float v = weight[o * 576 + idx] * style[b * 64 + idx / 9];
                sum += v * v;
            }
            #pragma unroll
            for (int off = 16; off; off >>= 1)
                sum += __shfl_xor_sync(0xffffffffu, sum, off);
            const float inv = rsqrtf(EPS_F + sum);

            const int ip = lane;                          // input pair 0..31
            const int i0 = 2 * ip;
            const int kc = ip >> 3;
            const int r  = ip & 7;
            const int t  = r & 3;
            const int hf = r >> 2;
            #pragma unroll
            for (int tap = 0; tap < 9; tap++) {
                const float v0 = weight[o * 576 + i0 * 9 + tap]
                                 * style[b * 64 + i0] * inv;
                const float v1 = weight[o * 576 + (i0 + 1) * 9 + tap]
                                 * style[b * 64 + i0 + 1] * inv;
                __half2 h = __floats2half2_rn(v0, v1);
                const int ks = tap * 4 + kc;
                g_wB[(size_t)b * 18432 + (size_t)((t * 36 + ks) * 64 + o) * 2 + hf] =
                    *reinterpret_cast<uint32_t*>(&h);
            }
        }
        if (bid < MOD_CTAS) {
            __threadfence();
            __syncthreads();
            if (tid == 0) red_release(&g_flags[128]);
        }

        // ---- transpose sweep: 128 stripes of (b, 16 rows); 1 item/thread ----
        const int t = bid * 256 + tid;                    // 0..32767
        const int yloc = t >> 11;                         // row within stripe
        const int rem  = t & 2047;
        const int x    = rem >> 2;                        // 0..511
        const int cg   = rem & 3;                         // channel group (16 ch)

        for (int s = 0; s < 128; s++) {
            const int b  = s >> 5;
            const int y  = ((s & 31) << 4) + yloc;
            const float* ipl = input + (((size_t)(b * 64 + cg * 16)) << 18)
                                     + ((size_t)y << 9) + x;
            uint32_t pk[8];
            #pragma unroll
            for (int j = 0; j < 8; j++) {
                const float a0 = ipl[(size_t)(2 * j) << 18];
                const float a1 = ipl[(size_t)(2 * j + 1) << 18];
                __half2 h = __floats2half2_rn(a0, a1);
                pk[j] = *reinterpret_cast<uint32_t*>(&h);
            }
            __half* dp = g_hwc + ((((size_t)(b * 512 + y) << 9) + x) << 6) + cg * 16;
            *reinterpret_cast<uint4*>(dp)     = make_uint4(pk[0], pk[1], pk[2], pk[3]);
            *reinterpret_cast<uint4*>(dp + 8) = make_uint4(pk[4], pk[5], pk[6], pk[7]);

            __threadfence();
            __syncthreads();
            if (tid == 0) red_release(&g_flags[s]);
        }
        return;
    }

    // =======================================================================
    // CONSUMER PATH: conv tile
    // =======================================================================
    extern __shared__ __align__(16) char dsm[];
    __half*    Ash = reinterpret_cast<__half*>(dsm);
    uint32_t*  Bsh = reinterpret_cast<uint32_t*>(dsm + ASH_BYTES);

    const int cidx = bid - N_PROD;
    const int b    = cidx >> 11;
    const int rem  = cidx & 2047;
    const int y0   = (rem >> 5) << 3;
    const int x0   = (rem & 31) << 4;

    // ---- wait for modulated weights, then load B tiles ----
    WAIT_GE(g_flags[128], (uint32_t)MOD_CTAS);
    {
        const uint4* src = reinterpret_cast<const uint4*>(g_wB + (size_t)b * 18432);
        #pragma unroll
        for (int it = 0; it < 18; it++) {                // 4608 uint4
            const int i4  = it * 256 + tid;
            const int t   = i4 / 1152;
            const int rm  = i4 - t * 1152;
            *(reinterpret_cast<uint4*>(Bsh + t * B_TSTRIDE) + rm) = src[i4];
        }
    }

    // ---- wait for the stripes covering rows y0-1 .. y0+8 ----
    {
        const int sy0 = (y0 == 0)   ? 0  : ((y0 - 1) >> 4);
        const int sy1 = (y0 == 504) ? 31 : ((y0 + 8) >> 4);
        WAIT_GE(g_flags[b * 32 + sy0], (uint32_t)N_PROD);
        WAIT_GE(g_flags[b * 32 + sy1], (uint32_t)N_PROD);
    }

    // ---- load 10x18 px halo (HWC fp16), zero-padded at borders ----
    {
        const __half* src_b = g_hwc + (size_t)b * (512 * 512 * 64);
        #pragma unroll
        for (int it = 0; it < 6; it++) {                 // 1440 items
            const int idx = it * 256 + tid;
            if (idx < 1440) {
                const int p  = idx >> 3;
                const int ck = idx & 7;
                const int r  = p / 18;
                const int c  = p - r * 18;
                const int gy = y0 - 1 + r;
                const int gx = x0 - 1 + c;
                uint4 v = make_uint4(0u, 0u, 0u, 0u);
                if ((unsigned)gy < 512u && (unsigned)gx < 512u)
                    v = *reinterpret_cast<const uint4*>(
                            src_b + ((size_t)gy * 512 + gx) * 64 + ck * 8);
                *reinterpret_cast<uint4*>(Ash + p * 72 + ck * 8) = v;
            }
        }
    }
    __syncthreads();

    const int wm = wid & 3;    // m: tile rows 2wm, 2wm+1
    const int wn = wid >> 2;   // n: o range [wn*32, wn*32+32)

    float acc[2][4][4];
    #pragma unroll
    for (int mi = 0; mi < 2; mi++)
        #pragma unroll
        for (int ni = 0; ni < 4; ni++)
            #pragma unroll
            for (int j = 0; j < 4; j++) acc[mi][ni][j] = 0.f;

    const uint32_t ashu = smem_u32(Ash);
    uint32_t aBase[2];
    #pragma unroll
    for (int mi = 0; mi < 2; mi++)
        aBase[mi] = ashu + (uint32_t)(((2 * wm + mi) * 18 + (lane & 15)) * 144)
                         + (uint32_t)((lane >> 4) * 16);

    const uint32_t* Blane = Bsh + (lane & 3) * B_TSTRIDE
                                + (wn * 32 + (lane >> 2)) * 2;

    #define A_ADDR(mi, ks) (aBase[mi] \
        + (uint32_t)(((((ks) >> 2) / 3) * 18 + (((ks) >> 2) % 3)) * 144) \
        + (uint32_t)(((ks) & 3) * 32))
    #define LDSM4(dst, addr) \
        asm volatile("ldmatrix.sync.aligned.m8n8.x4.shared.b16 {%0,%1,%2,%3}, [%4];" \
            : "=r"((dst)[0]), "=r"((dst)[1]), "=r"((dst)[2]), "=r"((dst)[3]) \
            : "r"(addr))

    uint32_t af[2][2][4];    // [parity][mi][frag]
    LDSM4(af[0][0], A_ADDR(0, 0));
    LDSM4(af[0][1], A_ADDR(1, 0));

    #pragma unroll
    for (int ks = 0; ks < 36; ks++) {
        const int cur = ks & 1;
        const int nxt = cur ^ 1;
        if (ks < 35) {                       // prefetch next step's A fragments
            LDSM4(af[nxt][0], A_ADDR(0, ks + 1));
            LDSM4(af[nxt][1], A_ADDR(1, ks + 1));
        }
        const uint32_t* Bks = Blane + ks * 128;
        uint2 bv[4];
        #pragma unroll
        for (int ni = 0; ni < 4; ni++)
            bv[ni] = *reinterpret_cast<const uint2*>(Bks + ni * 16);

        #pragma unroll
        for (int ni = 0; ni < 4; ni++)
            #pragma unroll
            for (int mi = 0; mi < 2; mi++)
                asm volatile(
                    "mma.sync.aligned.m16n8k16.row.col.f32.f16.f16.f32 "
                    "{%0,%1,%2,%3}, {%4,%5,%6,%7}, {%8,%9}, {%0,%1,%2,%3};"
                    : "+f"(acc[mi][ni][0]), "+f"(acc[mi][ni][1]),
                      "+f"(acc[mi][ni][2]), "+f"(acc[mi][ni][3])
                    : "r"(af[cur][mi][0]), "r"(af[cur][mi][1]),
                      "r"(af[cur][mi][2]), "r"(af[cur][mi][3]),
                      "r"(bv[ni].x), "r"(bv[ni].y));
    }
    #undef A_ADDR
    #undef LDSM4

    // ---- epilogue ----
    const int xg = x0 + (lane >> 2);
    const int og = wn * 32 + 2 * (lane & 3);
    #pragma unroll
    for (int mi = 0; mi < 2; mi++) {
        const int y = y0 + 2 * wm + mi;
        #pragma unroll
        for (int ni = 0; ni < 4; ni++) {
            float* p = out + ((size_t)(b * 64 + og + ni * 8) << 18)
                           + ((size_t)y << 9) + xg;
            p[0]               = acc[mi][ni][0];
            p[(size_t)1 << 18] = acc[mi][ni][1];
            p[8]               = acc[mi][ni][2];
            p[((size_t)1 << 18) + 8] = acc[mi][ni][3];
        }
    }
}

// ---------------------------------------------------------------------------
// Harness entry point.
//   d_in[0] = input  (4, 64, 512, 512) float
//   d_in[1] = style  (4, 64)           float
//   d_in[2] = weight (64, 64, 3, 3)    float
//   d_out   = (4, 64, 512, 512) float
// ---------------------------------------------------------------------------
extern "C" void kernel_launch(void* const* d_in, const int* in_sizes, int n_in,
                              void* d_out, int out_size) {
    const float* input  = (const float*)d_in[0];
    const float* style  = (const float*)d_in[1];
    const float* weight = (const float*)d_in[2];
    float* out = (float*)d_out;

    cudaFuncSetAttribute(fused_kernel, cudaFuncAttributeMaxDynamicSharedMemorySize,
                         CONV_SMEM);

    zero_flags_kernel<<<1, 256>>>();
    fused_kernel<<<N_PROD + N_CONS, 256, CONV_SMEM>>>(input, weight, style, out);
}